// round 3
// baseline (speedup 1.0000x reference)
#include <cuda_runtime.h>
#include <math.h>

#define B 8
#define D 256
#define T 2048
#define KNN 10
#define BETA 0.2f
#define THR 0.7f

// ---------------- scratch (device globals; no allocations allowed) ----------
__device__ float g_invn[B * T];
__device__ float g_xn[B * T * D];            // [B,T,D] normalized, 16 MB
__device__ float g_sim[B * T * T];           // [B,T,T], 128 MB
__device__ float g_rho[B * T];
__device__ float g_s[B * T];
__device__ int   g_cstart[B * T];            // per (b, rank): cluster start
__device__ int   g_clen[B * T];              // per (b, rank): cluster len

// ---------------- 1) row norms of x^T ---------------------------------------
__global__ void norm_kernel(const float* __restrict__ x) {
    int idx = blockIdx.x * blockDim.x + threadIdx.x;   // over B*T
    int b = idx / T, t = idx % T;
    const float* xb = x + (size_t)b * D * T;
    float s = 0.f;
#pragma unroll 8
    for (int d = 0; d < D; d++) {
        float v = xb[d * T + t];                        // coalesced across threads
        s += v * v;
    }
    g_invn[idx] = 1.0f / fmaxf(sqrtf(s), 1e-12f);
}

// ---------------- 2) transpose + normalize: x[B,D,T] -> xn[B,T,D] -----------
__global__ void transpose_kernel(const float* __restrict__ x) {
    __shared__ float sh[32][33];
    int b = blockIdx.z;
    int t0 = blockIdx.x * 32, d0 = blockIdx.y * 32;
    int tx = threadIdx.x, ty = threadIdx.y;
    const float* xb = x + (size_t)b * D * T;
#pragma unroll
    for (int q = 0; q < 4; q++) {
        int d = d0 + ty + q * 8;
        sh[ty + q * 8][tx] = xb[d * T + t0 + tx];
    }
    __syncthreads();
#pragma unroll
    for (int q = 0; q < 4; q++) {
        int t = t0 + ty + q * 8;
        g_xn[((size_t)b * T + t) * D + d0 + tx] = sh[tx][ty + q * 8] * g_invn[b * T + t];
    }
}

// ---------------- 3) sim = (xn @ xn^T + 1) * 0.5 ----------------------------
// 64x64 block tile, 256 threads, 4x4 per thread, BK=16.
__global__ void __launch_bounds__(256) gemm_sim_kernel() {
    int b = blockIdx.z;
    const float* Ab = g_xn + (size_t)b * T * D;
    float* C = g_sim + (size_t)b * T * T;
    int row0 = blockIdx.y * 64, col0 = blockIdx.x * 64;

    __shared__ float As[16][68];   // k-major, pad 68 keeps float4 alignment
    __shared__ float Bs[16][68];

    int tx = threadIdx.x & 15, ty = threadIdx.x >> 4;
    float acc[4][4];
#pragma unroll
    for (int i = 0; i < 4; i++)
#pragma unroll
        for (int j = 0; j < 4; j++) acc[i][j] = 0.f;

    int lr = threadIdx.x >> 2;           // 0..63 (row within tile)
    int lk = (threadIdx.x & 3) * 4;      // 0,4,8,12
    const float* aptr = Ab + (row0 + lr) * D + lk;
    const float* bptr = Ab + (col0 + lr) * D + lk;

    for (int k0 = 0; k0 < D; k0 += 16) {
        float4 av = *(const float4*)(aptr + k0);
        float4 bv = *(const float4*)(bptr + k0);
        As[lk + 0][lr] = av.x; As[lk + 1][lr] = av.y;
        As[lk + 2][lr] = av.z; As[lk + 3][lr] = av.w;
        Bs[lk + 0][lr] = bv.x; Bs[lk + 1][lr] = bv.y;
        Bs[lk + 2][lr] = bv.z; Bs[lk + 3][lr] = bv.w;
        __syncthreads();
#pragma unroll
        for (int kk = 0; kk < 16; kk++) {
            float4 a4 = *(const float4*)&As[kk][ty * 4];
            float4 b4 = *(const float4*)&Bs[kk][tx * 4];
            float a[4] = {a4.x, a4.y, a4.z, a4.w};
            float bb[4] = {b4.x, b4.y, b4.z, b4.w};
#pragma unroll
            for (int i = 0; i < 4; i++)
#pragma unroll
                for (int j = 0; j < 4; j++) acc[i][j] += a[i] * bb[j];
        }
        __syncthreads();
    }
#pragma unroll
    for (int i = 0; i < 4; i++) {
        float4 o;
        o.x = (acc[i][0] + 1.f) * 0.5f;
        o.y = (acc[i][1] + 1.f) * 0.5f;
        o.z = (acc[i][2] + 1.f) * 0.5f;
        o.w = (acc[i][3] + 1.f) * 0.5f;
        *(float4*)&C[(size_t)(row0 + ty * 4 + i) * T + col0 + tx * 4] = o;
    }
}

// ---------------- 4) rho: top-11 per row, drop max (self), exp(-mean) -------
__global__ void rho_kernel() {
    int gw = (blockIdx.x * blockDim.x + threadIdx.x) >> 5;  // row = b*T+i
    int lane = threadIdx.x & 31;
    const float* row = g_sim + (size_t)gw * T;

    float a[11];
#pragma unroll
    for (int k = 0; k < 11; k++) a[k] = -1e30f;

    for (int j = lane; j < T; j += 32) {
        float v = row[j];
        if (v > a[10]) {
#pragma unroll
            for (int k = 0; k < 11; k++) {
                if (v > a[k]) { float tmp = a[k]; a[k] = v; v = tmp; }
            }
        }
    }
    // merge 32 sorted lists: extract global max 11 times
    float sum = 0.f;
#pragma unroll
    for (int r = 0; r < 11; r++) {
        float h = a[0], m = h;
#pragma unroll
        for (int o = 16; o > 0; o >>= 1) m = fmaxf(m, __shfl_xor_sync(0xffffffffu, m, o));
        unsigned msk = __ballot_sync(0xffffffffu, h == m);
        int winner = __ffs(msk) - 1;
        if (lane == winner) {
#pragma unroll
            for (int k = 0; k < 10; k++) a[k] = a[k + 1];
            a[10] = -1e30f;
        }
        if (r > 0) sum += m;   // ranks 1..10 (rank 0 = self sim)
    }
    if (lane == 0) g_rho[gw] = expf(-sum * (1.0f / KNN));
}

// ---------------- 5) delta + s = rho*delta ----------------------------------
__global__ void delta_kernel() {
    __shared__ float rho_sh[T];
    int b = blockIdx.y;
    for (int j = threadIdx.x; j < T; j += blockDim.x) rho_sh[j] = g_rho[b * T + j];
    __syncthreads();

    int w = threadIdx.x >> 5, lane = threadIdx.x & 31;
    int i = blockIdx.x * 8 + w;
    float rho_i = rho_sh[i];
    const float* row = g_sim + ((size_t)b * T + i) * T;

    float mn = 1e30f, mx = -1e30f;
    bool any = false;
    for (int j = lane; j < T; j += 32) {
        float v = row[j];
        bool hi = rho_sh[j] > rho_i;
        if (hi) { mn = fminf(mn, v); any = true; }
        mx = fmaxf(mx, v);
    }
#pragma unroll
    for (int o = 16; o > 0; o >>= 1) {
        mn = fminf(mn, __shfl_xor_sync(0xffffffffu, mn, o));
        mx = fmaxf(mx, __shfl_xor_sync(0xffffffffu, mx, o));
    }
    any = __any_sync(0xffffffffu, any);
    if (lane == 0) {
        float delta = any ? mn : mx;
        g_s[b * T + i] = rho_i * delta;
    }
}

// ---------------- 6) clustering (one block per batch) -----------------------
// Shared layout (dynamic):
//   band[T*9] : sim[t][t-4..t+4]        73728 B
//   s_sh[T]                               8192 B
//   key[T]                                8192 B
//   ord[T]                                8192 B
//   lenA[T]                               8192 B
//   staA[T]                               8192 B
//   asg[T]   (uchar)                      2048 B
//   ncl                                      4 B
__device__ __forceinline__ void bitonic_sort_shared(float* key, int* ord) {
    for (int k = 2; k <= T; k <<= 1) {
        for (int j = k >> 1; j > 0; j >>= 1) {
            for (int i = threadIdx.x; i < T; i += blockDim.x) {
                int l = i ^ j;
                if (l > i) {
                    bool up = ((i & k) == 0);
                    float ki = key[i], kl = key[l];
                    int oi = ord[i], ol = ord[l];
                    bool iAfter = (ki > kl) || (ki == kl && oi > ol);
                    if (iAfter == up) {
                        key[i] = kl; key[l] = ki;
                        ord[i] = ol; ord[l] = oi;
                    }
                }
            }
            __syncthreads();
        }
    }
}

__global__ void __launch_bounds__(256) cluster_kernel(float* lens_out) {
    extern __shared__ char smem[];
    float* band = (float*)smem;
    float* s_sh = band + T * 9;
    float* key  = s_sh + T;
    int* ordA = (int*)(key + T);
    int* lenA = ordA + T;
    int* staA = lenA + T;
    unsigned char* asg = (unsigned char*)(staA + T);
    int* sh_ncl = (int*)(asg + T);

    int b = blockIdx.x;
    int tid = threadIdx.x;

    for (int t = tid; t < T; t += 256) {
        s_sh[t] = g_s[b * T + t];
        asg[t] = 0;
    }
    for (int idx = tid; idx < T * 9; idx += 256) {
        int t = idx / 9, o = idx % 9;
        int j = t - 4 + o;
        band[idx] = (j >= 0 && j < T) ? g_sim[((size_t)b * T + t) * T + j] : 0.f;
    }
    __syncthreads();

    // seed order = argsort(s desc, idx asc)
    for (int t = tid; t < T; t += 256) { key[t] = -s_sh[t]; ordA[t] = t; }
    __syncthreads();
    bitonic_sort_shared(key, ordA);

    // serial greedy phase: warp 0, all lanes redundantly compute identical state
    if (tid < 32) {
        int lane = tid;
        int p = 0, cid = 0, remaining = T;
        while (remaining > 0) {
            for (;;) {
                int idx = p + lane;
                bool un = (idx < T) && (asg[ordA[idx]] == 0);
                unsigned m = __ballot_sync(0xffffffffu, un);
                if (m) { p += __ffs(m) - 1; break; }
                p += 32;
            }
            int seed = ordA[p];
            asg[seed] = 1; remaining--;
            int size = 1, start = seed;
            bool alive = true;
#pragma unroll
            for (int off = 1; off <= 4; off++) {    // forward growth
                int t = seed + off;
                bool ok = alive && (t < T) && (size < 4);
                if (ok) ok = (asg[t] == 0) && (band[seed * 9 + 4 + off] - BETA * s_sh[t] > THR);
                if (ok) { asg[t] = 1; size++; remaining--; }
                alive = ok;
            }
            alive = true;
#pragma unroll
            for (int off = 1; off <= 4; off++) {    // backward growth
                int t = seed - off;
                bool ok = alive && (t >= 0) && (size < 4);
                if (ok) ok = (asg[t] == 0) && (band[seed * 9 + 4 - off] - BETA * s_sh[t] > THR);
                if (ok) { asg[t] = 1; start = t; size++; remaining--; }
                alive = ok;
            }
            lenA[cid] = size;
            staA[cid] = start;
            cid++;
        }
        if (lane == 0) *sh_ncl = cid;
    }
    __syncthreads();

    // rank clusters by start (stable: composite key start*4096+cid, exact < 2^24)
    int ncl = *sh_ncl;
    for (int c = tid; c < T; c += 256) {
        if (c >= ncl) { lenA[c] = 0; staA[c] = T; }
        key[c] = (float)(staA[c] * 4096 + c);
        ordA[c] = c;
    }
    __syncthreads();
    bitonic_sort_shared(key, ordA);

    for (int r = tid; r < T; r += 256) {
        int c = ordA[r];
        g_clen[b * T + r] = lenA[c];
        g_cstart[b * T + r] = staA[c];
        if (lens_out) lens_out[b * T + r] = (float)lenA[c];
    }
}

// ---------------- 7) mean-pool per cluster (members are contiguous) ---------
__global__ void pool_kernel(const float* __restrict__ x, float* __restrict__ out) {
    int idx = blockIdx.x * blockDim.x + threadIdx.x;   // over B*D*T
    int r = idx % T;
    int d = (idx / T) % D;
    int b = idx / (T * D);
    int len = g_clen[b * T + r];
    int st = g_cstart[b * T + r];
    float acc = 0.f;
    for (int k = 0; k < len; k++) acc += x[((size_t)b * D + d) * T + st + k];
    out[idx] = len ? acc / (float)len : 0.f;
}

// ---------------- launch -----------------------------------------------------
extern "C" void kernel_launch(void* const* d_in, const int* in_sizes, int n_in,
                              void* d_out, int out_size) {
    const float* x = (const float*)d_in[0];
    float* out = (float*)d_out;
    float* lens_out = (out_size >= (int)(B * D * T + B * T)) ? out + (size_t)B * D * T
                                                             : nullptr;

    cudaFuncSetAttribute(cluster_kernel,
                         cudaFuncAttributeMaxDynamicSharedMemorySize, 120 * 1024);

    norm_kernel<<<(B * T) / 256, 256>>>(x);
    transpose_kernel<<<dim3(T / 32, D / 32, B), dim3(32, 8)>>>(x);
    gemm_sim_kernel<<<dim3(T / 64, T / 64, B), 256>>>();
    rho_kernel<<<(B * T * 32) / 256, 256>>>();
    delta_kernel<<<dim3(T / 8, B), 256>>>();
    cluster_kernel<<<B, 256, 120 * 1024>>>(lens_out);
    pool_kernel<<<(B * D * T) / 256, 256>>>(x, out);
}

// round 5
// speedup vs baseline: 1.2791x; 1.2791x over previous
#include <cuda_runtime.h>
#include <cuda_bf16.h>
#include <math.h>

#define B 8
#define D 256
#define T 2048
#define KNN 10
#define BETA 0.2f
#define THR 0.7f

// ---------------- scratch (device globals; no allocations allowed) ----------
__device__ float g_invn[B * T];
__device__ __nv_bfloat16 g_xnb[B * T * D];   // [B,T,D] normalized bf16, 8 MB
__device__ float g_sim[B * T * T];           // [B,T,T], 128 MB
__device__ float g_rho[B * T];
__device__ float g_s[B * T];
__device__ int   g_cstart[B * T];
__device__ int   g_clen[B * T];

// ---------------- 1) row norms of x^T ---------------------------------------
__global__ void norm_kernel(const float* __restrict__ x) {
    int idx = blockIdx.x * blockDim.x + threadIdx.x;   // over B*T
    int b = idx / T, t = idx % T;
    const float* xb = x + (size_t)b * D * T;
    float s = 0.f;
#pragma unroll 8
    for (int d = 0; d < D; d++) {
        float v = xb[d * T + t];
        s += v * v;
    }
    g_invn[idx] = 1.0f / fmaxf(sqrtf(s), 1e-12f);
}

// ---------------- 2) transpose + normalize -> bf16 [B,T,D] ------------------
__global__ void transpose_kernel(const float* __restrict__ x) {
    __shared__ float sh[32][33];
    int b = blockIdx.z;
    int t0 = blockIdx.x * 32, d0 = blockIdx.y * 32;
    int tx = threadIdx.x, ty = threadIdx.y;
    const float* xb = x + (size_t)b * D * T;
#pragma unroll
    for (int q = 0; q < 4; q++) {
        int d = d0 + ty + q * 8;
        sh[ty + q * 8][tx] = xb[d * T + t0 + tx];
    }
    __syncthreads();
#pragma unroll
    for (int q = 0; q < 4; q++) {
        int t = t0 + ty + q * 8;
        g_xnb[((size_t)b * T + t) * D + d0 + tx] =
            __float2bfloat16(sh[tx][ty + q * 8] * g_invn[b * T + t]);
    }
}

// ---------------- 3) sim = (xn @ xn^T + 1) * 0.5 via bf16 HMMA ---------------
// 128x128 block tile, 8 warps (4m x 2n), warp tile 32x64, BK=32, 2-stage cp.async.
#define SKW 40   // smem row stride in bf16 (20 words -> conflict-free frag loads)

#define LOAD_STAGE(stage, k0)                                                        \
    {                                                                                \
        _Pragma("unroll")                                                            \
        for (int q = 0; q < 2; q++) {                                                \
            int idx = tid + q * 256;                                                 \
            int r = idx >> 2, c = idx & 3;                                           \
            const __nv_bfloat16* srcA = Ab + (size_t)(row0 + r) * D + (k0) + c * 8;  \
            unsigned dA = (unsigned)__cvta_generic_to_shared(                        \
                &As[stage][r * SKW + c * 8]);                                        \
            asm volatile("cp.async.cg.shared.global [%0], [%1], 16;\n"               \
                         :: "r"(dA), "l"(srcA));                                     \
            const __nv_bfloat16* srcB = Ab + (size_t)(col0 + r) * D + (k0) + c * 8;  \
            unsigned dB = (unsigned)__cvta_generic_to_shared(                        \
                &Bs[stage][r * SKW + c * 8]);                                        \
            asm volatile("cp.async.cg.shared.global [%0], [%1], 16;\n"               \
                         :: "r"(dB), "l"(srcB));                                     \
        }                                                                            \
        asm volatile("cp.async.commit_group;\n");                                    \
    }

__global__ void __launch_bounds__(256) gemm_sim_kernel(int b) {
    const __nv_bfloat16* Ab = g_xnb + (size_t)b * T * D;
    float* C = g_sim + (size_t)b * T * T;
    int row0 = blockIdx.y * 128, col0 = blockIdx.x * 128;

    __shared__ __nv_bfloat16 As[2][128 * SKW];
    __shared__ __nv_bfloat16 Bs[2][128 * SKW];

    int tid = threadIdx.x;
    int wid = tid >> 5, lane = tid & 31;
    int wm = wid >> 1, wn = wid & 1;        // 4 x 2 warp grid
    int g = lane >> 2, tg = lane & 3;

    float acc[2][8][4];
#pragma unroll
    for (int mt = 0; mt < 2; mt++)
#pragma unroll
        for (int nt = 0; nt < 8; nt++)
#pragma unroll
            for (int e = 0; e < 4; e++) acc[mt][nt][e] = 0.f;

    LOAD_STAGE(0, 0)

    for (int kt = 0; kt < 8; kt++) {
        if (kt < 7) {
            LOAD_STAGE((kt + 1) & 1, (kt + 1) * 32)
            asm volatile("cp.async.wait_group 1;\n");
        } else {
            asm volatile("cp.async.wait_group 0;\n");
        }
        __syncthreads();
        int st = kt & 1;
#pragma unroll
        for (int kk = 0; kk < 32; kk += 16) {
            unsigned af[2][4], bf[8][2];
#pragma unroll
            for (int mt = 0; mt < 2; mt++) {
                const __nv_bfloat16* base = &As[st][(wm * 32 + mt * 16 + g) * SKW + kk + tg * 2];
                af[mt][0] = *(const unsigned*)(base);
                af[mt][1] = *(const unsigned*)(base + 8 * SKW);
                af[mt][2] = *(const unsigned*)(base + 8);
                af[mt][3] = *(const unsigned*)(base + 8 * SKW + 8);
            }
#pragma unroll
            for (int nt = 0; nt < 8; nt++) {
                const __nv_bfloat16* base = &Bs[st][(wn * 64 + nt * 8 + g) * SKW + kk + tg * 2];
                bf[nt][0] = *(const unsigned*)(base);
                bf[nt][1] = *(const unsigned*)(base + 8);
            }
#pragma unroll
            for (int mt = 0; mt < 2; mt++)
#pragma unroll
                for (int nt = 0; nt < 8; nt++) {
                    asm volatile(
                        "mma.sync.aligned.m16n8k16.row.col.f32.bf16.bf16.f32 "
                        "{%0,%1,%2,%3},{%4,%5,%6,%7},{%8,%9},{%0,%1,%2,%3};\n"
                        : "+f"(acc[mt][nt][0]), "+f"(acc[mt][nt][1]),
                          "+f"(acc[mt][nt][2]), "+f"(acc[mt][nt][3])
                        : "r"(af[mt][0]), "r"(af[mt][1]), "r"(af[mt][2]), "r"(af[mt][3]),
                          "r"(bf[nt][0]), "r"(bf[nt][1]));
                }
        }
        __syncthreads();
    }

#pragma unroll
    for (int mt = 0; mt < 2; mt++) {
        int r = row0 + wm * 32 + mt * 16 + g;
#pragma unroll
        for (int nt = 0; nt < 8; nt++) {
            int c = col0 + wn * 64 + nt * 8 + tg * 2;
            float2 v0, v1;
            v0.x = (acc[mt][nt][0] + 1.f) * 0.5f;
            v0.y = (acc[mt][nt][1] + 1.f) * 0.5f;
            v1.x = (acc[mt][nt][2] + 1.f) * 0.5f;
            v1.y = (acc[mt][nt][3] + 1.f) * 0.5f;
            *(float2*)&C[(size_t)r * T + c] = v0;
            *(float2*)&C[(size_t)(r + 8) * T + c] = v1;
        }
    }
}

// ---------------- 4) rho: top-11 per row, drop max (self), exp(-mean) -------
__device__ __forceinline__ void ins11(float v, float* a) {
#pragma unroll
    for (int k = 0; k < 11; k++) {
        if (v > a[k]) { float tmp = a[k]; a[k] = v; v = tmp; }
    }
}

__global__ void rho_kernel(int b) {
    int i = (blockIdx.x * blockDim.x + threadIdx.x) >> 5;   // row within batch
    int lane = threadIdx.x & 31;
    const float4* row4 = (const float4*)(g_sim + ((size_t)b * T + i) * T);

    float a[11];
#pragma unroll
    for (int k = 0; k < 11; k++) a[k] = -1e30f;

    for (int j = lane; j < T / 4; j += 32) {
        float4 v = row4[j];
        float m = fmaxf(fmaxf(v.x, v.y), fmaxf(v.z, v.w));
        if (m > a[10]) {
            if (v.x > a[10]) ins11(v.x, a);
            if (v.y > a[10]) ins11(v.y, a);
            if (v.z > a[10]) ins11(v.z, a);
            if (v.w > a[10]) ins11(v.w, a);
        }
    }
    float sum = 0.f;
#pragma unroll
    for (int r = 0; r < 11; r++) {
        float h = a[0], m = h;
#pragma unroll
        for (int o = 16; o > 0; o >>= 1) m = fmaxf(m, __shfl_xor_sync(0xffffffffu, m, o));
        unsigned msk = __ballot_sync(0xffffffffu, h == m);
        int winner = __ffs(msk) - 1;
        if (lane == winner) {
#pragma unroll
            for (int k = 0; k < 10; k++) a[k] = a[k + 1];
            a[10] = -1e30f;
        }
        if (r > 0) sum += m;   // ranks 1..10 (rank 0 = self)
    }
    if (lane == 0) g_rho[b * T + i] = expf(-sum * (1.0f / KNN));
}

// ---------------- 5) delta + s = rho*delta ----------------------------------
__global__ void delta_kernel(int b) {
    __shared__ __align__(16) float rho_sh[T];
    for (int j = threadIdx.x; j < T; j += blockDim.x) rho_sh[j] = g_rho[b * T + j];
    __syncthreads();

    int w = threadIdx.x >> 5, lane = threadIdx.x & 31;
    int i = blockIdx.x * 8 + w;
    float rho_i = rho_sh[i];
    const float4* row4 = (const float4*)(g_sim + ((size_t)b * T + i) * T);
    const float4* rho4 = (const float4*)rho_sh;

    float mn = 1e30f, mx = -1e30f;
    bool any = false;
    for (int j = lane; j < T / 4; j += 32) {
        float4 v = row4[j];
        float4 r = rho4[j];
        if (r.x > rho_i) { mn = fminf(mn, v.x); any = true; }
        if (r.y > rho_i) { mn = fminf(mn, v.y); any = true; }
        if (r.z > rho_i) { mn = fminf(mn, v.z); any = true; }
        if (r.w > rho_i) { mn = fminf(mn, v.w); any = true; }
        mx = fmaxf(mx, fmaxf(fmaxf(v.x, v.y), fmaxf(v.z, v.w)));
    }
#pragma unroll
    for (int o = 16; o > 0; o >>= 1) {
        mn = fminf(mn, __shfl_xor_sync(0xffffffffu, mn, o));
        mx = fmaxf(mx, __shfl_xor_sync(0xffffffffu, mx, o));
    }
    any = __any_sync(0xffffffffu, any);
    if (lane == 0) {
        float delta = any ? mn : mx;
        g_s[b * T + i] = rho_i * delta;
    }
}

// ---------------- 6) clustering (one block per batch) -----------------------
__device__ __forceinline__ void bitonic_sort_shared(float* key, int* ord) {
    for (int k = 2; k <= T; k <<= 1) {
        for (int j = k >> 1; j > 0; j >>= 1) {
            for (int i = threadIdx.x; i < T; i += blockDim.x) {
                int l = i ^ j;
                if (l > i) {
                    bool up = ((i & k) == 0);
                    float ki = key[i], kl = key[l];
                    int oi = ord[i], ol = ord[l];
                    bool iAfter = (ki > kl) || (ki == kl && oi > ol);
                    if (iAfter == up) {
                        key[i] = kl; key[l] = ki;
                        ord[i] = ol; ord[l] = oi;
                    }
                }
            }
            __syncthreads();
        }
    }
}

__global__ void __launch_bounds__(256) cluster_kernel(float* lens_out) {
    extern __shared__ char smem[];
    float* band = (float*)smem;             // T*9
    float* s_sh = band + T * 9;
    float* key  = s_sh + T;
    int* ordA = (int*)(key + T);
    int* lenA = ordA + T;
    int* staA = lenA + T;
    unsigned char* asg = (unsigned char*)(staA + T);
    int* sh_ncl = (int*)(asg + T);

    int b = blockIdx.x;
    int tid = threadIdx.x;

    for (int t = tid; t < T; t += 256) {
        s_sh[t] = g_s[b * T + t];
        asg[t] = 0;
    }
    for (int idx = tid; idx < T * 9; idx += 256) {
        int t = idx / 9, o = idx % 9;
        int j = t - 4 + o;
        band[idx] = (j >= 0 && j < T) ? g_sim[((size_t)b * T + t) * T + j] : 0.f;
    }
    __syncthreads();

    for (int t = tid; t < T; t += 256) { key[t] = -s_sh[t]; ordA[t] = t; }
    __syncthreads();
    bitonic_sort_shared(key, ordA);

    if (tid < 32) {
        int lane = tid;
        int p = 0, cid = 0, remaining = T;
        while (remaining > 0) {
            for (;;) {
                int idx = p + lane;
                bool un = (idx < T) && (asg[ordA[idx]] == 0);
                unsigned m = __ballot_sync(0xffffffffu, un);
                if (m) { p += __ffs(m) - 1; break; }
                p += 32;
            }
            int seed = ordA[p];
            asg[seed] = 1; remaining--;
            int size = 1, start = seed;
            bool alive = true;
#pragma unroll
            for (int off = 1; off <= 4; off++) {    // forward
                int t = seed + off;
                bool ok = alive && (t < T) && (size < 4);
                if (ok) ok = (asg[t] == 0) && (band[seed * 9 + 4 + off] - BETA * s_sh[t] > THR);
                if (ok) { asg[t] = 1; size++; remaining--; }
                alive = ok;
            }
            alive = true;
#pragma unroll
            for (int off = 1; off <= 4; off++) {    // backward
                int t = seed - off;
                bool ok = alive && (t >= 0) && (size < 4);
                if (ok) ok = (asg[t] == 0) && (band[seed * 9 + 4 - off] - BETA * s_sh[t] > THR);
                if (ok) { asg[t] = 1; start = t; size++; remaining--; }
                alive = ok;
            }
            lenA[cid] = size;
            staA[cid] = start;
            cid++;
        }
        if (lane == 0) *sh_ncl = cid;
    }
    __syncthreads();

    int ncl = *sh_ncl;
    for (int c = tid; c < T; c += 256) {
        if (c >= ncl) { lenA[c] = 0; staA[c] = T; }
        key[c] = (float)(staA[c] * 4096 + c);   // stable by start, exact (< 2^24)
        ordA[c] = c;
    }
    __syncthreads();
    bitonic_sort_shared(key, ordA);

    for (int r = tid; r < T; r += 256) {
        int c = ordA[r];
        g_clen[b * T + r] = lenA[c];
        g_cstart[b * T + r] = staA[c];
        if (lens_out) lens_out[b * T + r] = (float)lenA[c];
    }
}

// ---------------- 7) mean-pool per cluster (members contiguous) -------------
__global__ void pool_kernel(const float* __restrict__ x, float* __restrict__ out) {
    int idx = blockIdx.x * blockDim.x + threadIdx.x;   // over B*D*T
    int r = idx % T;
    int d = (idx / T) % D;
    int b = idx / (T * D);
    int len = g_clen[b * T + r];
    int st = g_cstart[b * T + r];
    float acc = 0.f;
    for (int k = 0; k < len; k++) acc += x[((size_t)b * D + d) * T + st + k];
    out[idx] = len ? acc / (float)len : 0.f;
}

// ---------------- launch -----------------------------------------------------
extern "C" void kernel_launch(void* const* d_in, const int* in_sizes, int n_in,
                              void* d_out, int out_size) {
    const float* x = (const float*)d_in[0];
    float* out = (float*)d_out;
    float* lens_out = (out_size >= (int)(B * D * T + B * T)) ? out + (size_t)B * D * T
                                                             : nullptr;

    cudaFuncSetAttribute(cluster_kernel,
                         cudaFuncAttributeMaxDynamicSharedMemorySize, 120 * 1024);

    norm_kernel<<<(B * T) / 256, 256>>>(x);
    transpose_kernel<<<dim3(T / 32, D / 32, B), dim3(32, 8)>>>(x);
    // per-batch interleave: sim slice (16 MB) stays in L2 for rho/delta reads
    for (int b = 0; b < B; b++) {
        gemm_sim_kernel<<<dim3(T / 128, T / 128), 256>>>(b);
        rho_kernel<<<(T * 32) / 256, 256>>>(b);
        delta_kernel<<<T / 8, 256>>>(b);
    }
    cluster_kernel<<<B, 256, 120 * 1024>>>(lens_out);
    pool_kernel<<<(B * D * T) / 256, 256>>>(x, out);
}

// round 6
// speedup vs baseline: 1.4681x; 1.1477x over previous
#include <cuda_runtime.h>
#include <cuda_bf16.h>
#include <math.h>

#define B 8
#define D 256
#define T 2048
#define KNN 10
#define BETA 0.2f
#define THR 0.7f

// ---------------- scratch (device globals; no allocations allowed) ----------
__device__ float g_invn[B * T];
__device__ __nv_bfloat16 g_xnb[B * T * D];   // [B,T,D] normalized bf16, 8 MB
__device__ float g_sim[B * T * T];           // [B,T,T], 128 MB
__device__ float g_rho[B * T];
__device__ float g_s[B * T];
__device__ int   g_cstart[B * T];
__device__ int   g_clen[B * T];

// ---------------- 1) row norms of x^T ---------------------------------------
__global__ void norm_kernel(const float* __restrict__ x) {
    int idx = blockIdx.x * blockDim.x + threadIdx.x;   // over B*T
    int b = idx / T, t = idx % T;
    const float* xb = x + (size_t)b * D * T;
    float s = 0.f;
#pragma unroll 8
    for (int d = 0; d < D; d++) {
        float v = xb[d * T + t];
        s += v * v;
    }
    g_invn[idx] = 1.0f / fmaxf(sqrtf(s), 1e-12f);
}

// ---------------- 2) transpose + normalize -> bf16 [B,T,D] ------------------
__global__ void transpose_kernel(const float* __restrict__ x) {
    __shared__ float sh[32][33];
    int b = blockIdx.z;
    int t0 = blockIdx.x * 32, d0 = blockIdx.y * 32;
    int tx = threadIdx.x, ty = threadIdx.y;
    const float* xb = x + (size_t)b * D * T;
#pragma unroll
    for (int q = 0; q < 4; q++) {
        int d = d0 + ty + q * 8;
        sh[ty + q * 8][tx] = xb[d * T + t0 + tx];
    }
    __syncthreads();
#pragma unroll
    for (int q = 0; q < 4; q++) {
        int t = t0 + ty + q * 8;
        g_xnb[((size_t)b * T + t) * D + d0 + tx] =
            __float2bfloat16(sh[tx][ty + q * 8] * g_invn[b * T + t]);
    }
}

// ---------------- 3) sim = (xn @ xn^T + 1) * 0.5 via bf16 HMMA ---------------
// 128x128 block tile, 8 warps (4m x 2n), warp tile 32x64, BK=32, 2-stage cp.async.
#define SKW 40   // smem row stride in bf16 (20 words -> conflict-free frag loads)

#define LOAD_STAGE(stage, k0)                                                        \
    {                                                                                \
        _Pragma("unroll")                                                            \
        for (int q = 0; q < 2; q++) {                                                \
            int idx = tid + q * 256;                                                 \
            int r = idx >> 2, c = idx & 3;                                           \
            const __nv_bfloat16* srcA = Ab + (size_t)(row0 + r) * D + (k0) + c * 8;  \
            unsigned dA = (unsigned)__cvta_generic_to_shared(                        \
                &As[stage][r * SKW + c * 8]);                                        \
            asm volatile("cp.async.cg.shared.global [%0], [%1], 16;\n"               \
                         :: "r"(dA), "l"(srcA));                                     \
            const __nv_bfloat16* srcB = Ab + (size_t)(col0 + r) * D + (k0) + c * 8;  \
            unsigned dB = (unsigned)__cvta_generic_to_shared(                        \
                &Bs[stage][r * SKW + c * 8]);                                        \
            asm volatile("cp.async.cg.shared.global [%0], [%1], 16;\n"               \
                         :: "r"(dB), "l"(srcB));                                     \
        }                                                                            \
        asm volatile("cp.async.commit_group;\n");                                    \
    }

__global__ void __launch_bounds__(256) gemm_sim_kernel() {
    int b = blockIdx.z;
    const __nv_bfloat16* Ab = g_xnb + (size_t)b * T * D;
    float* C = g_sim + (size_t)b * T * T;
    int row0 = blockIdx.y * 128, col0 = blockIdx.x * 128;

    __shared__ __nv_bfloat16 As[2][128 * SKW];
    __shared__ __nv_bfloat16 Bs[2][128 * SKW];

    int tid = threadIdx.x;
    int wid = tid >> 5, lane = tid & 31;
    int wm = wid >> 1, wn = wid & 1;        // 4 x 2 warp grid
    int g = lane >> 2, tg = lane & 3;

    float acc[2][8][4];
#pragma unroll
    for (int mt = 0; mt < 2; mt++)
#pragma unroll
        for (int nt = 0; nt < 8; nt++)
#pragma unroll
            for (int e = 0; e < 4; e++) acc[mt][nt][e] = 0.f;

    LOAD_STAGE(0, 0)

    for (int kt = 0; kt < 8; kt++) {
        if (kt < 7) {
            LOAD_STAGE((kt + 1) & 1, (kt + 1) * 32)
            asm volatile("cp.async.wait_group 1;\n");
        } else {
            asm volatile("cp.async.wait_group 0;\n");
        }
        __syncthreads();
        int st = kt & 1;
#pragma unroll
        for (int kk = 0; kk < 32; kk += 16) {
            unsigned af[2][4], bf[8][2];
#pragma unroll
            for (int mt = 0; mt < 2; mt++) {
                const __nv_bfloat16* base = &As[st][(wm * 32 + mt * 16 + g) * SKW + kk + tg * 2];
                af[mt][0] = *(const unsigned*)(base);
                af[mt][1] = *(const unsigned*)(base + 8 * SKW);
                af[mt][2] = *(const unsigned*)(base + 8);
                af[mt][3] = *(const unsigned*)(base + 8 * SKW + 8);
            }
#pragma unroll
            for (int nt = 0; nt < 8; nt++) {
                const __nv_bfloat16* base = &Bs[st][(wn * 64 + nt * 8 + g) * SKW + kk + tg * 2];
                bf[nt][0] = *(const unsigned*)(base);
                bf[nt][1] = *(const unsigned*)(base + 8);
            }
#pragma unroll
            for (int mt = 0; mt < 2; mt++)
#pragma unroll
                for (int nt = 0; nt < 8; nt++) {
                    asm volatile(
                        "mma.sync.aligned.m16n8k16.row.col.f32.bf16.bf16.f32 "
                        "{%0,%1,%2,%3},{%4,%5,%6,%7},{%8,%9},{%0,%1,%2,%3};\n"
                        : "+f"(acc[mt][nt][0]), "+f"(acc[mt][nt][1]),
                          "+f"(acc[mt][nt][2]), "+f"(acc[mt][nt][3])
                        : "r"(af[mt][0]), "r"(af[mt][1]), "r"(af[mt][2]), "r"(af[mt][3]),
                          "r"(bf[nt][0]), "r"(bf[nt][1]));
                }
        }
        __syncthreads();
    }

#pragma unroll
    for (int mt = 0; mt < 2; mt++) {
        int r = row0 + wm * 32 + mt * 16 + g;
#pragma unroll
        for (int nt = 0; nt < 8; nt++) {
            int c = col0 + wn * 64 + nt * 8 + tg * 2;
            float2 v0, v1;
            v0.x = (acc[mt][nt][0] + 1.f) * 0.5f;
            v0.y = (acc[mt][nt][1] + 1.f) * 0.5f;
            v1.x = (acc[mt][nt][2] + 1.f) * 0.5f;
            v1.y = (acc[mt][nt][3] + 1.f) * 0.5f;
            *(float2*)&C[(size_t)r * T + c] = v0;
            *(float2*)&C[(size_t)(r + 8) * T + c] = v1;
        }
    }
}

// ---------------- 4) rho: top-11 per row, drop max (self), exp(-mean) -------
__device__ __forceinline__ void ins11(float v, float* a) {
#pragma unroll
    for (int k = 0; k < 11; k++) {
        if (v > a[k]) { float tmp = a[k]; a[k] = v; v = tmp; }
    }
}

__global__ void rho_kernel() {
    int row = (blockIdx.x * blockDim.x + threadIdx.x) >> 5;   // global row = b*T+i
    int lane = threadIdx.x & 31;
    const float4* row4 = (const float4*)(g_sim + (size_t)row * T);

    float a[11];
#pragma unroll
    for (int k = 0; k < 11; k++) a[k] = -1e30f;

    for (int j = lane; j < T / 4; j += 32) {
        float4 v = row4[j];
        float m = fmaxf(fmaxf(v.x, v.y), fmaxf(v.z, v.w));
        if (m > a[10]) {
            if (v.x > a[10]) ins11(v.x, a);
            if (v.y > a[10]) ins11(v.y, a);
            if (v.z > a[10]) ins11(v.z, a);
            if (v.w > a[10]) ins11(v.w, a);
        }
    }
    float sum = 0.f;
#pragma unroll
    for (int r = 0; r < 11; r++) {
        float h = a[0], m = h;
#pragma unroll
        for (int o = 16; o > 0; o >>= 1) m = fmaxf(m, __shfl_xor_sync(0xffffffffu, m, o));
        unsigned msk = __ballot_sync(0xffffffffu, h == m);
        int winner = __ffs(msk) - 1;
        if (lane == winner) {
#pragma unroll
            for (int k = 0; k < 10; k++) a[k] = a[k + 1];
            a[10] = -1e30f;
        }
        if (r > 0) sum += m;   // ranks 1..10 (rank 0 = self)
    }
    if (lane == 0) g_rho[row] = expf(-sum * (1.0f / KNN));
}

// ---------------- 5) delta + s = rho*delta ----------------------------------
__global__ void delta_kernel() {
    __shared__ __align__(16) float rho_sh[T];
    int b = blockIdx.y;
    for (int j = threadIdx.x; j < T; j += blockDim.x) rho_sh[j] = g_rho[b * T + j];
    __syncthreads();

    int w = threadIdx.x >> 5, lane = threadIdx.x & 31;
    int i = blockIdx.x * 8 + w;
    float rho_i = rho_sh[i];
    const float4* row4 = (const float4*)(g_sim + ((size_t)b * T + i) * T);
    const float4* rho4 = (const float4*)rho_sh;

    float mn = 1e30f, mx = -1e30f;
    bool any = false;
    for (int j = lane; j < T / 4; j += 32) {
        float4 v = row4[j];
        float4 r = rho4[j];
        if (r.x > rho_i) { mn = fminf(mn, v.x); any = true; }
        if (r.y > rho_i) { mn = fminf(mn, v.y); any = true; }
        if (r.z > rho_i) { mn = fminf(mn, v.z); any = true; }
        if (r.w > rho_i) { mn = fminf(mn, v.w); any = true; }
        mx = fmaxf(mx, fmaxf(fmaxf(v.x, v.y), fmaxf(v.z, v.w)));
    }
#pragma unroll
    for (int o = 16; o > 0; o >>= 1) {
        mn = fminf(mn, __shfl_xor_sync(0xffffffffu, mn, o));
        mx = fmaxf(mx, __shfl_xor_sync(0xffffffffu, mx, o));
    }
    any = __any_sync(0xffffffffu, any);
    if (lane == 0) {
        float delta = any ? mn : mx;
        g_s[b * T + i] = rho_i * delta;
    }
}

// ---------------- 6) clustering (one block of 1024 per batch) ---------------
__device__ __forceinline__ void bitonic_sort_shared(float* key, int* ord) {
    for (int k = 2; k <= T; k <<= 1) {
        for (int j = k >> 1; j > 0; j >>= 1) {
#pragma unroll 2
            for (int i = threadIdx.x; i < T; i += 1024) {
                int l = i ^ j;
                if (l > i) {
                    bool up = ((i & k) == 0);
                    float ki = key[i], kl = key[l];
                    int oi = ord[i], ol = ord[l];
                    bool iAfter = (ki > kl) || (ki == kl && oi > ol);
                    if (iAfter == up) {
                        key[i] = kl; key[l] = ki;
                        ord[i] = ol; ord[l] = oi;
                    }
                }
            }
            __syncthreads();
        }
    }
}

__global__ void __launch_bounds__(1024) cluster_kernel(float* lens_out) {
    extern __shared__ char smem[];
    float* band = (float*)smem;             // T*9
    float* s_sh = band + T * 9;
    float* key  = s_sh + T;
    int* ordA = (int*)(key + T);
    int* lenA = ordA + T;
    int* staA = lenA + T;
    unsigned char* asg = (unsigned char*)(staA + T);
    int* sh_ncl = (int*)(asg + T);

    int b = blockIdx.x;
    int tid = threadIdx.x;

    for (int t = tid; t < T; t += 1024) {
        s_sh[t] = g_s[b * T + t];
        asg[t] = 0;
    }
    for (int idx = tid; idx < T * 9; idx += 1024) {
        int t = idx / 9, o = idx % 9;
        int j = t - 4 + o;
        band[idx] = (j >= 0 && j < T) ? g_sim[((size_t)b * T + t) * T + j] : 0.f;
    }
    __syncthreads();

    for (int t = tid; t < T; t += 1024) { key[t] = -s_sh[t]; ordA[t] = t; }
    __syncthreads();
    bitonic_sort_shared(key, ordA);

    if (tid < 32) {
        int lane = tid;
        int p = 0, cid = 0, remaining = T;
        while (remaining > 0) {
            for (;;) {
                int idx = p + lane;
                bool un = (idx < T) && (asg[ordA[idx]] == 0);
                unsigned m = __ballot_sync(0xffffffffu, un);
                if (m) { p += __ffs(m) - 1; break; }
                p += 32;
            }
            int seed = ordA[p];
            asg[seed] = 1; remaining--;
            int size = 1, start = seed;
            bool alive = true;
#pragma unroll
            for (int off = 1; off <= 4; off++) {    // forward
                int t = seed + off;
                bool ok = alive && (t < T) && (size < 4);
                if (ok) ok = (asg[t] == 0) && (band[seed * 9 + 4 + off] - BETA * s_sh[t] > THR);
                if (ok) { asg[t] = 1; size++; remaining--; }
                alive = ok;
            }
            alive = true;
#pragma unroll
            for (int off = 1; off <= 4; off++) {    // backward
                int t = seed - off;
                bool ok = alive && (t >= 0) && (size < 4);
                if (ok) ok = (asg[t] == 0) && (band[seed * 9 + 4 - off] - BETA * s_sh[t] > THR);
                if (ok) { asg[t] = 1; start = t; size++; remaining--; }
                alive = ok;
            }
            lenA[cid] = size;
            staA[cid] = start;
            cid++;
        }
        if (lane == 0) *sh_ncl = cid;
    }
    __syncthreads();

    int ncl = *sh_ncl;
    for (int c = tid; c < T; c += 1024) {
        if (c >= ncl) { lenA[c] = 0; staA[c] = T; }
        key[c] = (float)(staA[c] * 4096 + c);   // stable by start, exact (< 2^24)
        ordA[c] = c;
    }
    __syncthreads();
    bitonic_sort_shared(key, ordA);

    for (int r = tid; r < T; r += 1024) {
        int c = ordA[r];
        g_clen[b * T + r] = lenA[c];
        g_cstart[b * T + r] = staA[c];
        if (lens_out) lens_out[b * T + r] = (float)lenA[c];
    }
}

// ---------------- 7) mean-pool per cluster (members contiguous) -------------
__global__ void pool_kernel(const float* __restrict__ x, float* __restrict__ out) {
    int idx = blockIdx.x * blockDim.x + threadIdx.x;   // over B*D*T
    int r = idx % T;
    int d = (idx / T) % D;
    int b = idx / (T * D);
    int len = g_clen[b * T + r];
    int st = g_cstart[b * T + r];
    float acc = 0.f;
    for (int k = 0; k < len; k++) acc += x[((size_t)b * D + d) * T + st + k];
    out[idx] = len ? acc / (float)len : 0.f;
}

// ---------------- launch -----------------------------------------------------
extern "C" void kernel_launch(void* const* d_in, const int* in_sizes, int n_in,
                              void* d_out, int out_size) {
    const float* x = (const float*)d_in[0];
    float* out = (float*)d_out;
    float* lens_out = (out_size >= (int)(B * D * T + B * T)) ? out + (size_t)B * D * T
                                                             : nullptr;

    cudaFuncSetAttribute(cluster_kernel,
                         cudaFuncAttributeMaxDynamicSharedMemorySize, 120 * 1024);

    norm_kernel<<<(B * T) / 256, 256>>>(x);
    transpose_kernel<<<dim3(T / 32, D / 32, B), dim3(32, 8)>>>(x);
    gemm_sim_kernel<<<dim3(T / 128, T / 128, B), 256>>>();
    rho_kernel<<<(B * T * 32) / 256, 256>>>();
    delta_kernel<<<dim3(T / 8, B), 256>>>();
    cluster_kernel<<<B, 1024, 120 * 1024>>>(lens_out);
    pool_kernel<<<(B * D * T) / 256, 256>>>(x, out);
}

// round 7
// speedup vs baseline: 5.0343x; 3.4291x over previous
#include <cuda_runtime.h>
#include <cuda_bf16.h>
#include <math.h>

#define B 8
#define D 256
#define T 2048
#define KNN 10
#define BETA 0.2f
#define THR 0.7f

// ---------------- scratch (device globals; no allocations allowed) ----------
__device__ float g_invn[B * T];
__device__ __nv_bfloat16 g_xnb[B * T * D];   // [B,T,D] normalized bf16, 8 MB
__device__ float g_sim[B * T * T];           // [B,T,T], 128 MB
__device__ float g_rho[B * T];
__device__ float g_s[B * T];
__device__ int   g_cstart[B * T];
__device__ int   g_clen[B * T];

// ---------------- 1) row norms of x^T ---------------------------------------
__global__ void norm_kernel(const float* __restrict__ x) {
    int idx = blockIdx.x * blockDim.x + threadIdx.x;   // over B*T
    int b = idx / T, t = idx % T;
    const float* xb = x + (size_t)b * D * T;
    float s = 0.f;
#pragma unroll 8
    for (int d = 0; d < D; d++) {
        float v = xb[d * T + t];
        s += v * v;
    }
    g_invn[idx] = 1.0f / fmaxf(sqrtf(s), 1e-12f);
}

// ---------------- 2) transpose + normalize -> bf16 [B,T,D] ------------------
__global__ void transpose_kernel(const float* __restrict__ x) {
    __shared__ float sh[32][33];
    int b = blockIdx.z;
    int t0 = blockIdx.x * 32, d0 = blockIdx.y * 32;
    int tx = threadIdx.x, ty = threadIdx.y;
    const float* xb = x + (size_t)b * D * T;
#pragma unroll
    for (int q = 0; q < 4; q++) {
        int d = d0 + ty + q * 8;
        sh[ty + q * 8][tx] = xb[d * T + t0 + tx];
    }
    __syncthreads();
#pragma unroll
    for (int q = 0; q < 4; q++) {
        int t = t0 + ty + q * 8;
        g_xnb[((size_t)b * T + t) * D + d0 + tx] =
            __float2bfloat16(sh[tx][ty + q * 8] * g_invn[b * T + t]);
    }
}

// ---------------- 3) sim = (xn @ xn^T + 1) * 0.5 via bf16 HMMA ---------------
#define SKW 40   // smem row stride in bf16 (20 words -> conflict-free frag loads)

#define LOAD_STAGE(stage, k0)                                                        \
    {                                                                                \
        _Pragma("unroll")                                                            \
        for (int q = 0; q < 2; q++) {                                                \
            int idx = tid + q * 256;                                                 \
            int r = idx >> 2, c = idx & 3;                                           \
            const __nv_bfloat16* srcA = Ab + (size_t)(row0 + r) * D + (k0) + c * 8;  \
            unsigned dA = (unsigned)__cvta_generic_to_shared(                        \
                &As[stage][r * SKW + c * 8]);                                        \
            asm volatile("cp.async.cg.shared.global [%0], [%1], 16;\n"               \
                         :: "r"(dA), "l"(srcA));                                     \
            const __nv_bfloat16* srcB = Ab + (size_t)(col0 + r) * D + (k0) + c * 8;  \
            unsigned dB = (unsigned)__cvta_generic_to_shared(                        \
                &Bs[stage][r * SKW + c * 8]);                                        \
            asm volatile("cp.async.cg.shared.global [%0], [%1], 16;\n"               \
                         :: "r"(dB), "l"(srcB));                                     \
        }                                                                            \
        asm volatile("cp.async.commit_group;\n");                                    \
    }

__global__ void __launch_bounds__(256) gemm_sim_kernel() {
    int b = blockIdx.z;
    const __nv_bfloat16* Ab = g_xnb + (size_t)b * T * D;
    float* C = g_sim + (size_t)b * T * T;
    int row0 = blockIdx.y * 128, col0 = blockIdx.x * 128;

    __shared__ __nv_bfloat16 As[2][128 * SKW];
    __shared__ __nv_bfloat16 Bs[2][128 * SKW];

    int tid = threadIdx.x;
    int wid = tid >> 5, lane = tid & 31;
    int wm = wid >> 1, wn = wid & 1;        // 4 x 2 warp grid
    int g = lane >> 2, tg = lane & 3;

    float acc[2][8][4];
#pragma unroll
    for (int mt = 0; mt < 2; mt++)
#pragma unroll
        for (int nt = 0; nt < 8; nt++)
#pragma unroll
            for (int e = 0; e < 4; e++) acc[mt][nt][e] = 0.f;

    LOAD_STAGE(0, 0)

    for (int kt = 0; kt < 8; kt++) {
        if (kt < 7) {
            LOAD_STAGE((kt + 1) & 1, (kt + 1) * 32)
            asm volatile("cp.async.wait_group 1;\n");
        } else {
            asm volatile("cp.async.wait_group 0;\n");
        }
        __syncthreads();
        int st = kt & 1;
#pragma unroll
        for (int kk = 0; kk < 32; kk += 16) {
            unsigned af[2][4], bf[8][2];
#pragma unroll
            for (int mt = 0; mt < 2; mt++) {
                const __nv_bfloat16* base = &As[st][(wm * 32 + mt * 16 + g) * SKW + kk + tg * 2];
                af[mt][0] = *(const unsigned*)(base);
                af[mt][1] = *(const unsigned*)(base + 8 * SKW);
                af[mt][2] = *(const unsigned*)(base + 8);
                af[mt][3] = *(const unsigned*)(base + 8 * SKW + 8);
            }
#pragma unroll
            for (int nt = 0; nt < 8; nt++) {
                const __nv_bfloat16* base = &Bs[st][(wn * 64 + nt * 8 + g) * SKW + kk + tg * 2];
                bf[nt][0] = *(const unsigned*)(base);
                bf[nt][1] = *(const unsigned*)(base + 8);
            }
#pragma unroll
            for (int mt = 0; mt < 2; mt++)
#pragma unroll
                for (int nt = 0; nt < 8; nt++) {
                    asm volatile(
                        "mma.sync.aligned.m16n8k16.row.col.f32.bf16.bf16.f32 "
                        "{%0,%1,%2,%3},{%4,%5,%6,%7},{%8,%9},{%0,%1,%2,%3};\n"
                        : "+f"(acc[mt][nt][0]), "+f"(acc[mt][nt][1]),
                          "+f"(acc[mt][nt][2]), "+f"(acc[mt][nt][3])
                        : "r"(af[mt][0]), "r"(af[mt][1]), "r"(af[mt][2]), "r"(af[mt][3]),
                          "r"(bf[nt][0]), "r"(bf[nt][1]));
                }
        }
        __syncthreads();
    }

#pragma unroll
    for (int mt = 0; mt < 2; mt++) {
        int r = row0 + wm * 32 + mt * 16 + g;
#pragma unroll
        for (int nt = 0; nt < 8; nt++) {
            int c = col0 + wn * 64 + nt * 8 + tg * 2;
            float2 v0, v1;
            v0.x = (acc[mt][nt][0] + 1.f) * 0.5f;
            v0.y = (acc[mt][nt][1] + 1.f) * 0.5f;
            v1.x = (acc[mt][nt][2] + 1.f) * 0.5f;
            v1.y = (acc[mt][nt][3] + 1.f) * 0.5f;
            *(float2*)&C[(size_t)r * T + c] = v0;
            *(float2*)&C[(size_t)(r + 8) * T + c] = v1;
        }
    }
}

// ---------------- 4) rho: top-11 per row, drop max (self), exp(-mean) -------
__device__ __forceinline__ void ins11(float v, float* a) {
#pragma unroll
    for (int k = 0; k < 11; k++) {
        if (v > a[k]) { float tmp = a[k]; a[k] = v; v = tmp; }
    }
}

__global__ void rho_kernel() {
    int row = (blockIdx.x * blockDim.x + threadIdx.x) >> 5;   // global row = b*T+i
    int lane = threadIdx.x & 31;
    const float4* row4 = (const float4*)(g_sim + (size_t)row * T);

    float a[11];
#pragma unroll
    for (int k = 0; k < 11; k++) a[k] = -1e30f;

    // 8 elements per step: 7-op max tree + 1 compare
    for (int j = lane * 2; j < T / 4; j += 64) {
        float4 v0 = row4[j];
        float4 v1 = row4[j + 1];
        float m = fmaxf(fmaxf(fmaxf(v0.x, v0.y), fmaxf(v0.z, v0.w)),
                        fmaxf(fmaxf(v1.x, v1.y), fmaxf(v1.z, v1.w)));
        if (m > a[10]) {
            if (v0.x > a[10]) ins11(v0.x, a);
            if (v0.y > a[10]) ins11(v0.y, a);
            if (v0.z > a[10]) ins11(v0.z, a);
            if (v0.w > a[10]) ins11(v0.w, a);
            if (v1.x > a[10]) ins11(v1.x, a);
            if (v1.y > a[10]) ins11(v1.y, a);
            if (v1.z > a[10]) ins11(v1.z, a);
            if (v1.w > a[10]) ins11(v1.w, a);
        }
    }
    float sum = 0.f;
#pragma unroll
    for (int r = 0; r < 11; r++) {
        float h = a[0], m = h;
#pragma unroll
        for (int o = 16; o > 0; o >>= 1) m = fmaxf(m, __shfl_xor_sync(0xffffffffu, m, o));
        unsigned msk = __ballot_sync(0xffffffffu, h == m);
        int winner = __ffs(msk) - 1;
        if (lane == winner) {
#pragma unroll
            for (int k = 0; k < 10; k++) a[k] = a[k + 1];
            a[10] = -1e30f;
        }
        if (r > 0) sum += m;   // ranks 1..10 (rank 0 = self)
    }
    if (lane == 0) g_rho[row] = expf(-sum * (1.0f / KNN));
}

// ---------------- 5) delta + s = rho*delta ----------------------------------
// Row max == diagonal (self-sim ~1.0; off-diag bounded well below) -> no max scan.
__global__ void delta_kernel() {
    __shared__ __align__(16) float rho_sh[T];
    int b = blockIdx.y;
    for (int j = threadIdx.x; j < T; j += blockDim.x) rho_sh[j] = g_rho[b * T + j];
    __syncthreads();

    int w = threadIdx.x >> 5, lane = threadIdx.x & 31;
    int i = blockIdx.x * 8 + w;
    float rho_i = rho_sh[i];
    const float* rowp = g_sim + ((size_t)b * T + i) * T;
    const float4* row4 = (const float4*)rowp;
    const float4* rho4 = (const float4*)rho_sh;

    float mn = 1e30f;
    for (int j = lane; j < T / 4; j += 32) {
        float4 v = row4[j];
        float4 r = rho4[j];
        if (r.x > rho_i) mn = fminf(mn, v.x);
        if (r.y > rho_i) mn = fminf(mn, v.y);
        if (r.z > rho_i) mn = fminf(mn, v.z);
        if (r.w > rho_i) mn = fminf(mn, v.w);
    }
#pragma unroll
    for (int o = 16; o > 0; o >>= 1)
        mn = fminf(mn, __shfl_xor_sync(0xffffffffu, mn, o));
    if (lane == 0) {
        float delta = (mn < 1e29f) ? mn : rowp[i];   // fallback = row max = diagonal
        g_s[b * T + i] = rho_i * delta;
    }
}

// ---------------- 6) clustering (one block of 1024 per batch) ---------------
__device__ __forceinline__ void bitonic_sort_shared(float* key, int* ord) {
    for (int k = 2; k <= T; k <<= 1) {
        for (int j = k >> 1; j > 0; j >>= 1) {
#pragma unroll 2
            for (int i = threadIdx.x; i < T; i += 1024) {
                int l = i ^ j;
                if (l > i) {
                    bool up = ((i & k) == 0);
                    float ki = key[i], kl = key[l];
                    int oi = ord[i], ol = ord[l];
                    bool iAfter = (ki > kl) || (ki == kl && oi > ol);
                    if (iAfter == up) {
                        key[i] = kl; key[l] = ki;
                        ord[i] = ol; ord[l] = oi;
                    }
                }
            }
            __syncthreads();
        }
    }
}

// dynamic smem layout: s_sh[T] | key[T] | ordA[T] | lenA[T] | staA[T] | thr[T]
//                      | asgw[66] | ncl    ->  (6*T + 67) * 4 = 49420 B
__global__ void __launch_bounds__(1024) cluster_kernel(float* lens_out) {
    extern __shared__ char smem[];
    float* s_sh = (float*)smem;
    float* key  = s_sh + T;
    int* ordA = (int*)(key + T);
    int* lenA = ordA + T;
    int* staA = lenA + T;
    unsigned* thr_sh = (unsigned*)(staA + T);
    unsigned* asgw = thr_sh + T;          // bitset, bit t stored at index t+32
    int* sh_ncl = (int*)(asgw + 66);

    int b = blockIdx.x;
    int tid = threadIdx.x;

    for (int t = tid; t < T; t += 1024) s_sh[t] = g_s[b * T + t];
    for (int t = tid; t < 66; t += 1024) asgw[t] = 0u;
    __syncthreads();

    // per-frame 9-bit neighbor-threshold mask: bit k <-> time t-4+k (k!=4)
    for (int t = tid; t < T; t += 1024) {
        unsigned m = 0;
        const float* row = g_sim + ((size_t)b * T + t) * T;
#pragma unroll
        for (int k = 0; k < 9; k++) {
            if (k == 4) continue;
            int j = t - 4 + k;
            if (j >= 0 && j < T && (row[j] - BETA * s_sh[j] > THR)) m |= 1u << k;
        }
        thr_sh[t] = m;
    }

    // seed order = argsort(s desc, idx asc)
    for (int t = tid; t < T; t += 1024) { key[t] = -s_sh[t]; ordA[t] = t; }
    __syncthreads();
    bitonic_sort_shared(key, ordA);

    // chunked greedy phase: warp 0, 32 sorted entries per chunk
    if (tid < 32) {
        const unsigned full = 0xffffffffu;
        int lane = tid;
        int cid_base = 0;
        for (int p = 0; p < T; p += 32) {
            int seed = ordA[p + lane];
            unsigned thrm = thr_sh[seed];
            int bitpos = seed + 28;                 // (seed-4)+32, always >= 28
            unsigned w0 = asgw[bitpos >> 5];
            unsigned w1 = asgw[(bitpos >> 5) + 1];
            unsigned A = (unsigned)(((((unsigned long long)w1 << 32) | w0)
                                     >> (bitpos & 31))) & 0x1FFu;
            bool pre = (A >> 4) & 1u;
            bool isfast = !pre && (thrm == 0u);
            bool isslow = !pre && (thrm != 0u);
            unsigned slowm = __ballot_sync(full, isslow);
            bool committed = false;
            int st = seed, sz = 1;

            if (slowm == 0u) {
                committed = isfast;                 // independent singletons
            } else {
                // exact serial turns over slow lanes only
                unsigned rem = slowm;
                while (rem) {
                    int i = __ffs(rem) - 1; rem &= rem - 1;
                    int wb_i = __shfl_sync(full, seed, i) - 4;
                    unsigned contrib = 0u;
                    int lo = -1, hi = -2;
                    if (committed) {                 // earlier slow commit
                        lo = max(st, wb_i); hi = min(st + sz - 1, wb_i + 8);
                    } else if (isfast && lane < i) { // fast seed bit (set either way)
                        lo = max(seed, wb_i); hi = min(seed, wb_i + 8);
                    }
                    if (lo <= hi) contrib = ((1u << (hi - lo + 1)) - 1u) << (lo - wb_i);
                    unsigned add = __reduce_or_sync(full, contrib);
                    if (lane == i) {
                        A |= add;
                        if (!((A >> 4) & 1u)) {
                            unsigned avail = thrm & ~A;
                            unsigned f4 = (avail >> 5) & 0xFu;
                            int f = min(__ffs(~f4) - 1, 3);
                            int size = 1 + f;
                            unsigned b4 = __brev(avail & 0xFu) >> 28;
                            int bb = min(__ffs(~b4) - 1, 4 - size);
                            st = seed - bb;
                            sz = size + bb;
                            committed = true;
                        }
                    }
                }
                // fast lanes: covered by an earlier slow interval?
                unsigned cm = slowm;
                bool covered = false;
                while (cm) {
                    int j = __ffs(cm) - 1; cm &= cm - 1;
                    int stj = __shfl_sync(full, st, j);
                    int szj = __shfl_sync(full, sz, j);
                    int cmj = __shfl_sync(full, (int)committed, j);
                    if (isfast && j < lane && cmj && seed >= stj && seed < stj + szj)
                        covered = true;
                }
                if (isfast && !covered) committed = true;
            }

            unsigned cmask = __ballot_sync(full, committed);
            if (committed) {
                int cid = cid_base + __popc(cmask & ((1u << lane) - 1u));
                lenA[cid] = sz;
                staA[cid] = st;
                int bp = st + 32;
                unsigned long long m64 = ((1ull << sz) - 1ull) << (bp & 31);
                atomicOr(&asgw[bp >> 5], (unsigned)m64);
                unsigned hiw = (unsigned)(m64 >> 32);
                if (hiw) atomicOr(&asgw[(bp >> 5) + 1], hiw);
            }
            cid_base += __popc(cmask);
            __syncwarp(full);
        }
        if (lane == 0) *sh_ncl = cid_base;
    }
    __syncthreads();

    // rank clusters by start (stable: composite key start*4096+cid, exact < 2^24)
    int ncl = *sh_ncl;
    for (int c = tid; c < T; c += 1024) {
        if (c >= ncl) { lenA[c] = 0; staA[c] = T; }
        key[c] = (float)(staA[c] * 4096 + c);
        ordA[c] = c;
    }
    __syncthreads();
    bitonic_sort_shared(key, ordA);

    for (int r = tid; r < T; r += 1024) {
        int c = ordA[r];
        g_clen[b * T + r] = lenA[c];
        g_cstart[b * T + r] = staA[c];
        if (lens_out) lens_out[b * T + r] = (float)lenA[c];
    }
}

// ---------------- 7) mean-pool per cluster (members contiguous) -------------
__global__ void pool_kernel(const float* __restrict__ x, float* __restrict__ out) {
    int idx = blockIdx.x * blockDim.x + threadIdx.x;   // over B*D*T
    int r = idx % T;
    int d = (idx / T) % D;
    int b = idx / (T * D);
    int len = g_clen[b * T + r];
    int st = g_cstart[b * T + r];
    float acc = 0.f;
    for (int k = 0; k < len; k++) acc += x[((size_t)b * D + d) * T + st + k];
    out[idx] = len ? acc / (float)len : 0.f;
}

// ---------------- launch -----------------------------------------------------
extern "C" void kernel_launch(void* const* d_in, const int* in_sizes, int n_in,
                              void* d_out, int out_size) {
    const float* x = (const float*)d_in[0];
    float* out = (float*)d_out;
    float* lens_out = (out_size >= (int)(B * D * T + B * T)) ? out + (size_t)B * D * T
                                                             : nullptr;

    const int CLU_SMEM = (6 * T + 67) * 4;
    cudaFuncSetAttribute(cluster_kernel,
                         cudaFuncAttributeMaxDynamicSharedMemorySize, CLU_SMEM);

    norm_kernel<<<(B * T) / 256, 256>>>(x);
    transpose_kernel<<<dim3(T / 32, D / 32, B), dim3(32, 8)>>>(x);
    gemm_sim_kernel<<<dim3(T / 128, T / 128, B), 256>>>();
    rho_kernel<<<(B * T * 32) / 256, 256>>>();
    delta_kernel<<<dim3(T / 8, B), 256>>>();
    cluster_kernel<<<B, 1024, CLU_SMEM>>>(lens_out);
    pool_kernel<<<(B * D * T) / 256, 256>>>(x, out);
}